// round 3
// baseline (speedup 1.0000x reference)
#include <cuda_runtime.h>
#include <cuda_bf16.h>
#include <math.h>

// ---------------- Problem-size constants (fixed by the dataset) -------------
#define NMAX   40000
#define EMAX   640000
#define ETMAX  (EMAX + NMAX)      // edges + self loops
#define CIN    256
#define HDIM   256
#define COUT   512

// ---------------- Static device scratch (no allocation allowed) -------------
__device__ float g_bufA[(size_t)NMAX * HDIM];
__device__ float g_bufB[(size_t)NMAX * HDIM];
__device__ float g_bufH[(size_t)NMAX * HDIM];
__device__ float g_asrc[NMAX];
__device__ float g_adst[NMAX];
__device__ int   g_deg[NMAX];
__device__ int   g_off[NMAX + 1];
__device__ int   g_cursor[NMAX];
__device__ int   g_srcs[ETMAX];
__device__ int   g_is64;          // 1 if edge_index is int64, 0 if int32

// Buffer-id resolution (device side; host cannot take symbol addresses
// inside a graph-captured kernel_launch).
#define BUF_A 0
#define BUF_B 1
#define BUF_H 2
#define BUF_EXT (-1)

__device__ __forceinline__ float* resolve_buf(int id, float* ext)
{
    switch (id) {
        case BUF_A: return g_bufA;
        case BUF_B: return g_bufB;
        case BUF_H: return g_bufH;
        default:    return ext;
    }
}
__device__ __forceinline__ const float* resolve_cbuf(int id, const float* ext)
{
    switch (id) {
        case BUF_A: return g_bufA;
        case BUF_B: return g_bufB;
        case BUF_H: return g_bufH;
        default:    return ext;
    }
}

// Read edge endpoint idx (0..2E-1 flattened) honoring detected dtype.
__device__ __forceinline__ int edge_at(const void* ei, long long flat)
{
    if (g_is64) return (int)((const long long*)ei)[flat];
    return ((const int*)ei)[flat];
}

// =====================================================================
// Detect edge_index dtype.  Samples only the first 64 int64-interpreted
// words (in-bounds under both layouts).  int64 data holds valid node ids
// (< n); int32 data interpreted as int64 packs two indices -> huge.
// =====================================================================
__global__ void detect_dtype_kernel(const void* ei, int n)
{
    if (threadIdx.x == 0 && blockIdx.x == 0) {
        const long long* p = (const long long*)ei;
        int ok = 1;
        for (int i = 0; i < 64; i++) {
            long long v = p[i];
            if (v < 0 || v >= n) { ok = 0; break; }
        }
        g_is64 = ok;
    }
}

// =====================================================================
// GroupNorm(groups = C/8) + ELU.  One warp per node; each lane owns one
// 8-channel group, so stats need no cross-lane communication. C == 256.
// =====================================================================
__global__ void gnelu_kernel(int in_id, const float* __restrict__ in_ext,
                             const float* __restrict__ w,
                             const float* __restrict__ b,
                             int out_id, int n)
{
    const float* in = resolve_cbuf(in_id, in_ext);
    float* out = resolve_buf(out_id, nullptr);
    int warp = (blockIdx.x * blockDim.x + threadIdx.x) >> 5;
    int lane = threadIdx.x & 31;
    if (warp >= n) return;
    const float* row = in + (size_t)warp * 256;
    int c0 = lane * 8;
    float4 v0 = *(const float4*)(row + c0);
    float4 v1 = *(const float4*)(row + c0 + 4);
    float v[8] = {v0.x, v0.y, v0.z, v0.w, v1.x, v1.y, v1.z, v1.w};
    float mu = 0.f;
#pragma unroll
    for (int i = 0; i < 8; i++) mu += v[i];
    mu *= 0.125f;
    float var = 0.f;
#pragma unroll
    for (int i = 0; i < 8; i++) { float d = v[i] - mu; var += d * d; }
    var *= 0.125f;
    float inv = rsqrtf(var + 1e-5f);
    float* orow = out + (size_t)warp * 256;
#pragma unroll
    for (int i = 0; i < 8; i++) {
        float y = (v[i] - mu) * inv * w[c0 + i] + b[c0 + i];
        y = (y > 0.f) ? y : expm1f(y);
        v[i] = y;
    }
    *(float4*)(orow + c0)     = make_float4(v[0], v[1], v[2], v[3]);
    *(float4*)(orow + c0 + 4) = make_float4(v[4], v[5], v[6], v[7]);
}

// =====================================================================
// GEMM:  C[n][j] = sum_k A[n][k] * W[j][k]  (+ bias[j]) (+= if ACC)
// A: [N,K] row-major, W: [J,K] row-major.  BM=BN=64, BK=16, 256 thr,
// each thread computes a 4x4 micro-tile.
// =====================================================================
template <bool ACC, bool BIAS>
__global__ void gemm_nt_kernel(int A_id, const float* __restrict__ A_ext,
                               const float* __restrict__ W,
                               const float* __restrict__ bias,
                               int C_id, float* __restrict__ C_ext,
                               int N, int K, int J)
{
    const float* A = resolve_cbuf(A_id, A_ext);
    float* C = resolve_buf(C_id, C_ext);

    __shared__ float As[16][64];
    __shared__ float Ws[16][64];
    int bm = blockIdx.y * 64;
    int bj = blockIdx.x * 64;
    int tid = threadIdx.x;
    int tx = tid & 15;        // 0..15 -> column group
    int ty = tid >> 4;        // 0..15 -> row group
    int lr = tid >> 2;        // loader row   0..63
    int lc = (tid & 3) * 4;   // loader col4  0,4,8,12

    float acc[4][4] = {};

    for (int k0 = 0; k0 < K; k0 += 16) {
        int arow = bm + lr;
        float4 av = (arow < N) ? *(const float4*)(A + (size_t)arow * K + k0 + lc)
                               : make_float4(0.f, 0.f, 0.f, 0.f);
        float4 wv = *(const float4*)(W + (size_t)(bj + lr) * K + k0 + lc);
        As[lc + 0][lr] = av.x; As[lc + 1][lr] = av.y;
        As[lc + 2][lr] = av.z; As[lc + 3][lr] = av.w;
        Ws[lc + 0][lr] = wv.x; Ws[lc + 1][lr] = wv.y;
        Ws[lc + 2][lr] = wv.z; Ws[lc + 3][lr] = wv.w;
        __syncthreads();
#pragma unroll
        for (int kk = 0; kk < 16; kk++) {
            float a0 = As[kk][ty * 4 + 0];
            float a1 = As[kk][ty * 4 + 1];
            float a2 = As[kk][ty * 4 + 2];
            float a3 = As[kk][ty * 4 + 3];
            float b0 = Ws[kk][tx * 4 + 0];
            float b1 = Ws[kk][tx * 4 + 1];
            float b2 = Ws[kk][tx * 4 + 2];
            float b3 = Ws[kk][tx * 4 + 3];
            acc[0][0] += a0 * b0; acc[0][1] += a0 * b1; acc[0][2] += a0 * b2; acc[0][3] += a0 * b3;
            acc[1][0] += a1 * b0; acc[1][1] += a1 * b1; acc[1][2] += a1 * b2; acc[1][3] += a1 * b3;
            acc[2][0] += a2 * b0; acc[2][1] += a2 * b1; acc[2][2] += a2 * b2; acc[2][3] += a2 * b3;
            acc[3][0] += a3 * b0; acc[3][1] += a3 * b1; acc[3][2] += a3 * b2; acc[3][3] += a3 * b3;
        }
        __syncthreads();
    }

#pragma unroll
    for (int i = 0; i < 4; i++) {
        int row = bm + ty * 4 + i;
        if (row >= N) continue;
#pragma unroll
        for (int j = 0; j < 4; j++) {
            int col = bj + tx * 4 + j;
            float v = acc[i][j];
            if (BIAS) v += bias[col];
            if (ACC)  C[(size_t)row * J + col] += v;
            else      C[(size_t)row * J + col] = v;
        }
    }
}

// =====================================================================
// Per-node attention projections on h = g_bufH:
//   g_asrc[n] = h[n].a_src,  g_adst[n] = h[n].a_dst.   One warp per node.
// =====================================================================
__global__ void node_dots_kernel(const float* __restrict__ a_src,
                                 const float* __restrict__ a_dst, int n)
{
    int warp = (blockIdx.x * blockDim.x + threadIdx.x) >> 5;
    int lane = threadIdx.x & 31;
    if (warp >= n) return;
    const float* row = g_bufH + (size_t)warp * 256;
    float s1 = 0.f, s2 = 0.f;
#pragma unroll
    for (int i = 0; i < 8; i++) {
        int c = lane + i * 32;
        float v = row[c];
        s1 += v * a_src[c];
        s2 += v * a_dst[c];
    }
#pragma unroll
    for (int o = 16; o; o >>= 1) {
        s1 += __shfl_down_sync(0xffffffff, s1, o);
        s2 += __shfl_down_sync(0xffffffff, s2, o);
    }
    if (lane == 0) { g_asrc[warp] = s1; g_adst[warp] = s2; }
}

// ------------------------- CSR build kernels --------------------------------
__global__ void zero_deg_kernel(int n)
{
    int i = blockIdx.x * blockDim.x + threadIdx.x;
    if (i < n) g_deg[i] = 0;
}

__global__ void hist_kernel(const void* __restrict__ ei, int E, int n)
{
    int t = blockIdx.x * blockDim.x + threadIdx.x;
    if (t >= E + n) return;
    int d = (t < E) ? edge_at(ei, (long long)E + t) : (t - E);
    if ((unsigned)d >= (unsigned)n) return;   // safety clamp
    atomicAdd(&g_deg[d], 1);
}

// single-block exclusive scan: 1024 threads, each handles a contiguous chunk
__global__ void scan_kernel(int n)
{
    __shared__ int sh[1024];
    int tid = threadIdx.x;
    int per = (n + 1023) / 1024;
    int beg = tid * per;
    int end = min(n, beg + per);
    int sum = 0;
    for (int i = beg; i < end; i++) sum += g_deg[i];
    sh[tid] = sum;
    __syncthreads();
    for (int st = 1; st < 1024; st <<= 1) {
        int v = (tid >= st) ? sh[tid - st] : 0;
        __syncthreads();
        sh[tid] += v;
        __syncthreads();
    }
    int run = sh[tid] - sum;   // exclusive prefix
    for (int i = beg; i < end; i++) {
        g_off[i] = run;
        g_cursor[i] = run;
        run += g_deg[i];
    }
    if (tid == 1023) g_off[n] = sh[1023];
}

__global__ void scatter_kernel(const void* __restrict__ ei, int E, int n)
{
    int t = blockIdx.x * blockDim.x + threadIdx.x;
    if (t >= E + n) return;
    int s, d;
    if (t < E) {
        s = edge_at(ei, t);
        d = edge_at(ei, (long long)E + t);
    } else {
        s = t - E; d = t - E;
    }
    if ((unsigned)d >= (unsigned)n || (unsigned)s >= (unsigned)n) return;  // safety
    int p = atomicAdd(&g_cursor[d], 1);
    g_srcs[p] = s;
}

// =====================================================================
// GAT aggregation: per destination node, segment softmax over incoming
// edges + weighted sum of source rows of h = g_bufH.  One block
// (256 thr) per node; thread t owns channel t.
// =====================================================================
__global__ void gat_agg_kernel(const float* __restrict__ bias, int out_id, int n)
{
    float* out = resolve_buf(out_id, nullptr);
    int node = blockIdx.x;
    int tid  = threadIdx.x;
    int s0 = g_off[node], s1 = g_off[node + 1];
    float ad = g_adst[node];

    __shared__ float red[256];

    // pass 1: max over edges
    float m = -1e30f;
    for (int j = s0 + tid; j < s1; j += 256) {
        float e = g_asrc[g_srcs[j]] + ad;
        e = (e > 0.f) ? e : 0.2f * e;
        m = fmaxf(m, e);
    }
    red[tid] = m;
    __syncthreads();
    for (int st = 128; st; st >>= 1) {
        if (tid < st) red[tid] = fmaxf(red[tid], red[tid + st]);
        __syncthreads();
    }
    m = red[0];
    __syncthreads();

    // pass 2: sum of exp
    float s = 0.f;
    for (int j = s0 + tid; j < s1; j += 256) {
        float e = g_asrc[g_srcs[j]] + ad;
        e = (e > 0.f) ? e : 0.2f * e;
        s += expf(e - m);
    }
    red[tid] = s;
    __syncthreads();
    for (int st = 128; st; st >>= 1) {
        if (tid < st) red[tid] += red[tid + st];
        __syncthreads();
    }
    s = red[0];
    __syncthreads();
    float rinv = 1.0f / (s + 1e-16f);

    // pass 3: weighted accumulate (chunks of 128 edges staged in smem)
    __shared__ float alpha_sh[128];
    __shared__ int   src_sh[128];
    float acc = 0.f;
    for (int base = s0; base < s1; base += 128) {
        int cnt = min(128, s1 - base);
        if (tid < cnt) {
            int sn = g_srcs[base + tid];
            src_sh[tid] = sn;
            float e = g_asrc[sn] + ad;
            e = (e > 0.f) ? e : 0.2f * e;
            alpha_sh[tid] = expf(e - m) * rinv;
        }
        __syncthreads();
        for (int j = 0; j < cnt; j++)
            acc += g_bufH[(size_t)src_sh[j] * 256 + tid] * alpha_sh[j];
        __syncthreads();
    }
    out[(size_t)node * 256 + tid] = acc + bias[tid];
}

// ============================== launcher =====================================
extern "C" void kernel_launch(void* const* d_in, const int* in_sizes, int n_in,
                              void* d_out, int out_size)
{
    const float* x      = (const float*)d_in[0];
    const void*  ei     = d_in[1];
    const float* pre_w  = (const float*)d_in[2];
    const float* pre_b  = (const float*)d_in[3];
    const float* lin1_w = (const float*)d_in[4];
    const float* lin1_b = (const float*)d_in[5];
    const float* n1_w   = (const float*)d_in[6];
    const float* n1_b   = (const float*)d_in[7];
    const float* g1_w   = (const float*)d_in[8];
    const float* g1_as  = (const float*)d_in[9];
    const float* g1_ad  = (const float*)d_in[10];
    const float* g1_b   = (const float*)d_in[11];
    const float* n2_w   = (const float*)d_in[12];
    const float* n2_b   = (const float*)d_in[13];
    const float* g2_w   = (const float*)d_in[14];
    const float* g2_as  = (const float*)d_in[15];
    const float* g2_ad  = (const float*)d_in[16];
    const float* g2_b   = (const float*)d_in[17];
    const float* n3_w   = (const float*)d_in[18];
    const float* n3_b   = (const float*)d_in[19];
    const float* lin2_w = (const float*)d_in[20];
    const float* lin2_b = (const float*)d_in[21];
    const float* skip_w = (const float*)d_in[22];
    const float* skip_b = (const float*)d_in[23];
    float* out = (float*)d_out;

    int N = in_sizes[0] / CIN;
    int E = in_sizes[1] / 2;
    int ET = E + N;

    int warpBlocks = (N * 32 + 255) / 256;
    int eBlocks    = (ET + 255) / 256;
    int nBlocks    = (N + 255) / 256;

    // ---- edge dtype detection + CSR build (reused by both GAT layers) ----
    detect_dtype_kernel<<<1, 32>>>(ei, N);
    zero_deg_kernel<<<nBlocks, 256>>>(N);
    hist_kernel<<<eBlocks, 256>>>(ei, E, N);
    scan_kernel<<<1, 1024>>>(N);
    scatter_kernel<<<eBlocks, 256>>>(ei, E, N);

    // ---- pre_norm + ELU : x -> bufA ----
    gnelu_kernel<<<warpBlocks, 256>>>(BUF_EXT, x, pre_w, pre_b, BUF_A, N);

    // ---- lin1 + GN + ELU : bufA -> bufB ----
    gemm_nt_kernel<false, true><<<dim3(HDIM / 64, (N + 63) / 64), 256>>>(
        BUF_A, nullptr, lin1_w, lin1_b, BUF_B, nullptr, N, CIN, HDIM);
    gnelu_kernel<<<warpBlocks, 256>>>(BUF_B, nullptr, n1_w, n1_b, BUF_B, N);

    // ---- GAT layer 1 : bufB -> (h=bufH) -> bufA ----
    gemm_nt_kernel<false, false><<<dim3(HDIM / 64, (N + 63) / 64), 256>>>(
        BUF_B, nullptr, g1_w, nullptr, BUF_H, nullptr, N, HDIM, HDIM);
    node_dots_kernel<<<warpBlocks, 256>>>(g1_as, g1_ad, N);
    gat_agg_kernel<<<N, 256>>>(g1_b, BUF_A, N);
    gnelu_kernel<<<warpBlocks, 256>>>(BUF_A, nullptr, n2_w, n2_b, BUF_A, N);

    // ---- GAT layer 2 : bufA -> (h=bufH) -> bufB ----
    gemm_nt_kernel<false, false><<<dim3(HDIM / 64, (N + 63) / 64), 256>>>(
        BUF_A, nullptr, g2_w, nullptr, BUF_H, nullptr, N, HDIM, HDIM);
    node_dots_kernel<<<warpBlocks, 256>>>(g2_as, g2_ad, N);
    gat_agg_kernel<<<N, 256>>>(g2_b, BUF_B, N);
    gnelu_kernel<<<warpBlocks, 256>>>(BUF_B, nullptr, n3_w, n3_b, BUF_B, N);

    // ---- lin2 into out, then add skip GEMM ----
    gemm_nt_kernel<false, true><<<dim3(COUT / 64, (N + 63) / 64), 256>>>(
        BUF_B, nullptr, lin2_w, lin2_b, BUF_EXT, out, N, HDIM, COUT);
    gemm_nt_kernel<true, true><<<dim3(COUT / 64, (N + 63) / 64), 256>>>(
        BUF_EXT, x, skip_w, skip_b, BUF_EXT, out, N, CIN, COUT);
}

// round 9
// speedup vs baseline: 1.0400x; 1.0400x over previous
#include <cuda_runtime.h>
#include <cuda_bf16.h>
#include <math.h>
#include <stdint.h>

// ---------------- Problem-size constants (fixed by the dataset) -------------
#define NMAX   40000
#define EMAX   640000
#define ETMAX  (EMAX + NMAX)      // edges + self loops
#define CIN    256
#define HDIM   256
#define COUT   512
#define KDIM   256                // every GEMM in this model has K = 256

// ---------------- Static device scratch (no allocation allowed) -------------
__device__ float g_bufA[(size_t)NMAX * HDIM];
__device__ float g_bufB[(size_t)NMAX * HDIM];
__device__ float g_bufH[(size_t)NMAX * HDIM];
__device__ float g_asrc[NMAX];
__device__ float g_adst[NMAX];
__device__ int   g_deg[NMAX];
__device__ int   g_off[NMAX + 1];
__device__ int   g_cursor[NMAX];
__device__ int   g_srcs[ETMAX];
__device__ int   g_is64;          // 1 if edge_index is int64, 0 if int32

// Buffer-id resolution (device side; host cannot take symbol addresses
// inside a graph-captured kernel_launch).
#define BUF_A 0
#define BUF_B 1
#define BUF_H 2
#define BUF_EXT (-1)

__device__ __forceinline__ float* resolve_buf(int id, float* ext)
{
    switch (id) {
        case BUF_A: return g_bufA;
        case BUF_B: return g_bufB;
        case BUF_H: return g_bufH;
        default:    return ext;
    }
}
__device__ __forceinline__ const float* resolve_cbuf(int id, const float* ext)
{
    switch (id) {
        case BUF_A: return g_bufA;
        case BUF_B: return g_bufB;
        case BUF_H: return g_bufH;
        default:    return ext;
    }
}

// ---------------- tf32 helpers ----------------------------------------------
__device__ __forceinline__ uint32_t f32_to_tf32(float a)
{
    uint32_t r;
    asm("cvt.rna.tf32.f32 %0, %1;" : "=r"(r) : "f"(a));
    return r;
}
// split a = hi + lo, both tf32-representable
__device__ __forceinline__ void tf32_split(float a, uint32_t& hi, uint32_t& lo)
{
    hi = f32_to_tf32(a);
    float res = a - __uint_as_float(hi);
    lo = f32_to_tf32(res);
}

__device__ __forceinline__ void mma_tf32(float& c0, float& c1, float& c2, float& c3,
                                         uint32_t a0, uint32_t a1, uint32_t a2, uint32_t a3,
                                         uint32_t b0, uint32_t b1)
{
    asm volatile(
        "mma.sync.aligned.m16n8k8.row.col.f32.tf32.tf32.f32 "
        "{%0,%1,%2,%3}, {%4,%5,%6,%7}, {%8,%9}, {%0,%1,%2,%3};"
        : "+f"(c0), "+f"(c1), "+f"(c2), "+f"(c3)
        : "r"(a0), "r"(a1), "r"(a2), "r"(a3), "r"(b0), "r"(b1));
}

// =====================================================================
// 3xTF32 tensor-core GEMM:  C[m][j] = sum_k A[m][k] * W[j][k]
//   A: [Nrows, 256] row-major,  W: [J, 256] row-major.
// Tile BM=128, BN=64, BK=16; 256 threads = 8 warps in 4(M) x 2(N);
// each warp computes 32x32 via 2x4 m16n8k8 fragments, 3 passes
// (hi*hi, hi*lo, lo*hi) for ~fp32 accuracy.
// =====================================================================
#define BKP 18   // padded K stride (floats) for conflict-free LDS

template <bool ACC, bool BIAS>
__global__ void __launch_bounds__(256)
mmagemm_kernel(int A_id, const float* __restrict__ A_ext,
               const float* __restrict__ W,
               const float* __restrict__ bias,
               int C_id, float* __restrict__ C_ext,
               int Nrows, int J)
{
    const float* A = resolve_cbuf(A_id, A_ext);
    float* C = resolve_buf(C_id, C_ext);

    __shared__ uint32_t As_hi[128 * BKP];
    __shared__ uint32_t As_lo[128 * BKP];
    __shared__ uint32_t Bs_hi[64 * BKP];
    __shared__ uint32_t Bs_lo[64 * BKP];

    int tid  = threadIdx.x;
    int wid  = tid >> 5;
    int lane = tid & 31;
    int grp  = lane >> 2;      // 0..7
    int qid  = lane & 3;       // 0..3

    int m0 = blockIdx.y * 128;
    int j0 = blockIdx.x * 64;

    int warp_m = wid >> 1;     // 0..3 -> 32-row slab
    int warp_n = wid & 1;      // 0..1 -> 32-col slab
    int wm = warp_m * 32;
    int wn = warp_n * 32;

    // accumulators: 2 m-tiles x 4 n-tiles x 4 floats
    float acc[2][4][4];
#pragma unroll
    for (int i = 0; i < 2; i++)
#pragma unroll
        for (int j = 0; j < 4; j++)
#pragma unroll
            for (int q = 0; q < 4; q++) acc[i][j][q] = 0.f;

    // loader mapping
    int a_row  = tid >> 1;         // 0..127
    int a_half = tid & 1;          // k offset 0 / 8
    int b_row  = tid >> 2;         // 0..63
    int b_q    = tid & 3;          // k offset 0,4,8,12
    int a_grow = m0 + a_row;
    bool a_ok  = (a_grow < Nrows);
    const float* aptr = A + (size_t)a_grow * KDIM + a_half * 8;
    const float* bptr = W + (size_t)(j0 + b_row) * KDIM + b_q * 4;

    for (int k0 = 0; k0 < KDIM; k0 += 16) {
        // ---- load + split A tile (128x16) ----
        float4 av0 = a_ok ? *(const float4*)(aptr + k0)     : make_float4(0.f,0.f,0.f,0.f);
        float4 av1 = a_ok ? *(const float4*)(aptr + k0 + 4) : make_float4(0.f,0.f,0.f,0.f);
        {
            float va[8] = {av0.x, av0.y, av0.z, av0.w, av1.x, av1.y, av1.z, av1.w};
            uint32_t* ph = As_hi + a_row * BKP + a_half * 8;
            uint32_t* pl = As_lo + a_row * BKP + a_half * 8;
#pragma unroll
            for (int i = 0; i < 8; i++) {
                uint32_t h, l;
                tf32_split(va[i], h, l);
                ph[i] = h; pl[i] = l;
            }
        }
        // ---- load + split B tile (64x16) ----
        {
            float4 bv = *(const float4*)(bptr + k0);
            float vb[4] = {bv.x, bv.y, bv.z, bv.w};
            uint32_t* ph = Bs_hi + b_row * BKP + b_q * 4;
            uint32_t* pl = Bs_lo + b_row * BKP + b_q * 4;
#pragma unroll
            for (int i = 0; i < 4; i++) {
                uint32_t h, l;
                tf32_split(vb[i], h, l);
                ph[i] = h; pl[i] = l;
            }
        }
        __syncthreads();

        // ---- compute: 2 k-steps of 8 ----
#pragma unroll
        for (int ks = 0; ks < 2; ks++) {
            int kk = ks * 8;
            // A fragments (hi & lo) for 2 m-tiles
            uint32_t ah[2][4], al[2][4];
#pragma unroll
            for (int mt = 0; mt < 2; mt++) {
                int r0 = (wm + mt * 16 + grp) * BKP + kk + qid;
                int r1 = (wm + mt * 16 + grp + 8) * BKP + kk + qid;
                ah[mt][0] = As_hi[r0];     ah[mt][1] = As_hi[r1];
                ah[mt][2] = As_hi[r0 + 4]; ah[mt][3] = As_hi[r1 + 4];
                al[mt][0] = As_lo[r0];     al[mt][1] = As_lo[r1];
                al[mt][2] = As_lo[r0 + 4]; al[mt][3] = As_lo[r1 + 4];
            }
            // B fragments (hi & lo) for 4 n-tiles
            uint32_t bh[4][2], bl[4][2];
#pragma unroll
            for (int nt = 0; nt < 4; nt++) {
                int rb = (wn + nt * 8 + grp) * BKP + kk + qid;
                bh[nt][0] = Bs_hi[rb]; bh[nt][1] = Bs_hi[rb + 4];
                bl[nt][0] = Bs_lo[rb]; bl[nt][1] = Bs_lo[rb + 4];
            }
#pragma unroll
            for (int mt = 0; mt < 2; mt++) {
#pragma unroll
                for (int nt = 0; nt < 4; nt++) {
                    float* c = acc[mt][nt];
                    // hi*hi
                    mma_tf32(c[0], c[1], c[2], c[3],
                             ah[mt][0], ah[mt][1], ah[mt][2], ah[mt][3],
                             bh[nt][0], bh[nt][1]);
                    // hi*lo
                    mma_tf32(c[0], c[1], c[2], c[3],
                             ah[mt][0], ah[mt][1], ah[mt][2], ah[mt][3],
                             bl[nt][0], bl[nt][1]);
                    // lo*hi
                    mma_tf32(c[0], c[1], c[2], c[3],
                             al[mt][0], al[mt][1], al[mt][2], al[mt][3],
                             bh[nt][0], bh[nt][1]);
                }
            }
        }
        __syncthreads();
    }

    // ---- epilogue ----
#pragma unroll
    for (int mt = 0; mt < 2; mt++) {
        int row0 = m0 + wm + mt * 16 + grp;
        int row1 = row0 + 8;
#pragma unroll
        for (int nt = 0; nt < 4; nt++) {
            int col = j0 + wn + nt * 8 + qid * 2;
            float b0 = 0.f, b1 = 0.f;
            if (BIAS) { b0 = bias[col]; b1 = bias[col + 1]; }
            if (row0 < Nrows) {
                float* p = C + (size_t)row0 * J + col;
                float v0 = acc[mt][nt][0] + b0;
                float v1 = acc[mt][nt][1] + b1;
                if (ACC) { v0 += p[0]; v1 += p[1]; }
                p[0] = v0; p[1] = v1;
            }
            if (row1 < Nrows) {
                float* p = C + (size_t)row1 * J + col;
                float v2 = acc[mt][nt][2] + b0;
                float v3 = acc[mt][nt][3] + b1;
                if (ACC) { v2 += p[0]; v3 += p[1]; }
                p[0] = v2; p[1] = v3;
            }
        }
    }
}

// Read edge endpoint idx (0..2E-1 flattened) honoring detected dtype.
__device__ __forceinline__ int edge_at(const void* ei, long long flat)
{
    if (g_is64) return (int)((const long long*)ei)[flat];
    return ((const int*)ei)[flat];
}

__global__ void detect_dtype_kernel(const void* ei, int n)
{
    if (threadIdx.x == 0 && blockIdx.x == 0) {
        const long long* p = (const long long*)ei;
        int ok = 1;
        for (int i = 0; i < 64; i++) {
            long long v = p[i];
            if (v < 0 || v >= n) { ok = 0; break; }
        }
        g_is64 = ok;
    }
}

// =====================================================================
// GroupNorm(groups = C/8) + ELU.  One warp per node; each lane owns one
// 8-channel group. C == 256.
// =====================================================================
__global__ void gnelu_kernel(int in_id, const float* __restrict__ in_ext,
                             const float* __restrict__ w,
                             const float* __restrict__ b,
                             int out_id, int n)
{
    const float* in = resolve_cbuf(in_id, in_ext);
    float* out = resolve_buf(out_id, nullptr);
    int warp = (blockIdx.x * blockDim.x + threadIdx.x) >> 5;
    int lane = threadIdx.x & 31;
    if (warp >= n) return;
    const float* row = in + (size_t)warp * 256;
    int c0 = lane * 8;
    float4 v0 = *(const float4*)(row + c0);
    float4 v1 = *(const float4*)(row + c0 + 4);
    float v[8] = {v0.x, v0.y, v0.z, v0.w, v1.x, v1.y, v1.z, v1.w};
    float mu = 0.f;
#pragma unroll
    for (int i = 0; i < 8; i++) mu += v[i];
    mu *= 0.125f;
    float var = 0.f;
#pragma unroll
    for (int i = 0; i < 8; i++) { float d = v[i] - mu; var += d * d; }
    var *= 0.125f;
    float inv = rsqrtf(var + 1e-5f);
    float* orow = out + (size_t)warp * 256;
#pragma unroll
    for (int i = 0; i < 8; i++) {
        float y = (v[i] - mu) * inv * w[c0 + i] + b[c0 + i];
        y = (y > 0.f) ? y : expm1f(y);
        v[i] = y;
    }
    *(float4*)(orow + c0)     = make_float4(v[0], v[1], v[2], v[3]);
    *(float4*)(orow + c0 + 4) = make_float4(v[4], v[5], v[6], v[7]);
}

// =====================================================================
// Per-node attention projections on h = g_bufH.  One warp per node.
// =====================================================================
__global__ void node_dots_kernel(const float* __restrict__ a_src,
                                 const float* __restrict__ a_dst, int n)
{
    int warp = (blockIdx.x * blockDim.x + threadIdx.x) >> 5;
    int lane = threadIdx.x & 31;
    if (warp >= n) return;
    const float* row = g_bufH + (size_t)warp * 256;
    float s1 = 0.f, s2 = 0.f;
#pragma unroll
    for (int i = 0; i < 8; i++) {
        int c = lane + i * 32;
        float v = row[c];
        s1 += v * a_src[c];
        s2 += v * a_dst[c];
    }
#pragma unroll
    for (int o = 16; o; o >>= 1) {
        s1 += __shfl_down_sync(0xffffffff, s1, o);
        s2 += __shfl_down_sync(0xffffffff, s2, o);
    }
    if (lane == 0) { g_asrc[warp] = s1; g_adst[warp] = s2; }
}

// ------------------------- CSR build kernels --------------------------------
__global__ void zero_deg_kernel(int n)
{
    int i = blockIdx.x * blockDim.x + threadIdx.x;
    if (i < n) g_deg[i] = 0;
}

__global__ void hist_kernel(const void* __restrict__ ei, int E, int n)
{
    int t = blockIdx.x * blockDim.x + threadIdx.x;
    if (t >= E + n) return;
    int d = (t < E) ? edge_at(ei, (long long)E + t) : (t - E);
    if ((unsigned)d >= (unsigned)n) return;
    atomicAdd(&g_deg[d], 1);
}

// single-block exclusive scan: shfl warp scan, 2 barriers total
__global__ void scan_kernel(int n)
{
    __shared__ int warp_sums[32];
    int tid = threadIdx.x;           // 1024 threads
    int lane = tid & 31, wid = tid >> 5;
    int per = (n + 1023) >> 10;
    int beg = tid * per;
    int end = min(n, beg + per);
    int sum = 0;
    for (int i = beg; i < end; i++) sum += g_deg[i];
    int v = sum;
#pragma unroll
    for (int o = 1; o < 32; o <<= 1) {
        int t = __shfl_up_sync(0xffffffff, v, o);
        if (lane >= o) v += t;
    }
    if (lane == 31) warp_sums[wid] = v;
    __syncthreads();
    if (wid == 0) {
        int w = warp_sums[lane];
#pragma unroll
        for (int o = 1; o < 32; o <<= 1) {
            int t = __shfl_up_sync(0xffffffff, w, o);
            if (lane >= o) w += t;
        }
        warp_sums[lane] = w;
    }
    __syncthreads();
    int run = v - sum + (wid ? warp_sums[wid - 1] : 0);  // exclusive prefix
    for (int i = beg; i < end; i++) {
        g_off[i] = run;
        g_cursor[i] = run;
        run += g_deg[i];
    }
    if (tid == 0) g_off[n] = warp_sums[31];
}

__global__ void scatter_kernel(const void* __restrict__ ei, int E, int n)
{
    int t = blockIdx.x * blockDim.x + threadIdx.x;
    if (t >= E + n) return;
    int s, d;
    if (t < E) {
        s = edge_at(ei, t);
        d = edge_at(ei, (long long)E + t);
    } else {
        s = t - E; d = t - E;
    }
    if ((unsigned)d >= (unsigned)n || (unsigned)s >= (unsigned)n) return;
    int p = atomicAdd(&g_cursor[d], 1);
    g_srcs[p] = s;
}

// =====================================================================
// GAT aggregation: per destination node, segment softmax over incoming
// edges + weighted sum of source rows of h = g_bufH.  One block
// (256 thr) per node; thread t owns channel t.
// =====================================================================
__global__ void gat_agg_kernel(const float* __restrict__ bias, int out_id, int n)
{
    float* out = resolve_buf(out_id, nullptr);
    int node = blockIdx.x;
    int tid  = threadIdx.x;
    int s0 = g_off[node], s1 = g_off[node + 1];
    float ad = g_adst[node];

    __shared__ float red[256];

    float m = -1e30f;
    for (int j = s0 + tid; j < s1; j += 256) {
        float e = g_asrc[g_srcs[j]] + ad;
        e = (e > 0.f) ? e : 0.2f * e;
        m = fmaxf(m, e);
    }
    red[tid] = m;
    __syncthreads();
    for (int st = 128; st; st >>= 1) {
        if (tid < st) red[tid] = fmaxf(red[tid], red[tid + st]);
        __syncthreads();
    }
    m = red[0];
    __syncthreads();

    float s = 0.f;
    for (int j = s0 + tid; j < s1; j += 256) {
        float e = g_asrc[g_srcs[j]] + ad;
        e = (e > 0.f) ? e : 0.2f * e;
        s += expf(e - m);
    }
    red[tid] = s;
    __syncthreads();
    for (int st = 128; st; st >>= 1) {
        if (tid < st) red[tid] += red[tid + st];
        __syncthreads();
    }
    s = red[0];
    __syncthreads();
    float rinv = 1.0f / (s + 1e-16f);

    __shared__ float alpha_sh[128];
    __shared__ int   src_sh[128];
    float acc = 0.f;
    for (int base = s0; base < s1; base += 128) {
        int cnt = min(128, s1 - base);
        if (tid < cnt) {
            int sn = g_srcs[base + tid];
            src_sh[tid] = sn;
            float e = g_asrc[sn] + ad;
            e = (e > 0.f) ? e : 0.2f * e;
            alpha_sh[tid] = expf(e - m) * rinv;
        }
        __syncthreads();
        for (int j = 0; j < cnt; j++)
            acc += g_bufH[(size_t)src_sh[j] * 256 + tid] * alpha_sh[j];
        __syncthreads();
    }
    out[(size_t)node * 256 + tid] = acc + bias[tid];
}

// ============================== launcher =====================================
extern "C" void kernel_launch(void* const* d_in, const int* in_sizes, int n_in,
                              void* d_out, int out_size)
{
    const float* x      = (const float*)d_in[0];
    const void*  ei     = d_in[1];
    const float* pre_w  = (const float*)d_in[2];
    const float* pre_b  = (const float*)d_in[3];
    const float* lin1_w = (const float*)d_in[4];
    const float* lin1_b = (const float*)d_in[5];
    const float* n1_w   = (const float*)d_in[6];
    const float* n1_b   = (const float*)d_in[7];
    const float* g1_w   = (const float*)d_in[8];
    const float* g1_as  = (const float*)d_in[9];
    const float* g1_ad  = (const float*)d_in[10];
    const float* g1_b   = (const float*)d_in[11];
    const float* n2_w   = (const float*)d_in[12];
    const float* n2_b   = (const float*)d_in[13];
    const float* g2_w   = (const float*)d_in[14];
    const float* g2_as  = (const float*)d_in[15];
    const float* g2_ad  = (const float*)d_in[16];
    const float* g2_b   = (const float*)d_in[17];
    const float* n3_w   = (const float*)d_in[18];
    const float* n3_b   = (const float*)d_in[19];
    const float* lin2_w = (const float*)d_in[20];
    const float* lin2_b = (const float*)d_in[21];
    const float* skip_w = (const float*)d_in[22];
    const float* skip_b = (const float*)d_in[23];
    float* out = (float*)d_out;

    int N = in_sizes[0] / CIN;
    int E = in_sizes[1] / 2;
    int ET = E + N;

    int warpBlocks = (N * 32 + 255) / 256;
    int eBlocks    = (ET + 255) / 256;
    int nBlocks    = (N + 255) / 256;
    int mBlocks    = (N + 127) / 128;

    // ---- edge dtype detection + CSR build ----
    detect_dtype_kernel<<<1, 32>>>(ei, N);
    zero_deg_kernel<<<nBlocks, 256>>>(N);
    hist_kernel<<<eBlocks, 256>>>(ei, E, N);
    scan_kernel<<<1, 1024>>>(N);
    scatter_kernel<<<eBlocks, 256>>>(ei, E, N);

    // ---- skip GEMM first (writes out; 6th launch -> gets ncu profiled) ----
    mmagemm_kernel<false, true><<<dim3(COUT / 64, mBlocks), 256>>>(
        BUF_EXT, x, skip_w, skip_b, BUF_EXT, out, N, COUT);

    // ---- pre_norm + ELU : x -> bufA ----
    gnelu_kernel<<<warpBlocks, 256>>>(BUF_EXT, x, pre_w, pre_b, BUF_A, N);

    // ---- lin1 + GN + ELU : bufA -> bufB ----
    mmagemm_kernel<false, true><<<dim3(HDIM / 64, mBlocks), 256>>>(
        BUF_A, nullptr, lin1_w, lin1_b, BUF_B, nullptr, N, HDIM);
    gnelu_kernel<<<warpBlocks, 256>>>(BUF_B, nullptr, n1_w, n1_b, BUF_B, N);

    // ---- GAT layer 1 : bufB -> (h=bufH) -> bufA ----
    mmagemm_kernel<false, false><<<dim3(HDIM / 64, mBlocks), 256>>>(
        BUF_B, nullptr, g1_w, nullptr, BUF_H, nullptr, N, HDIM);
    node_dots_kernel<<<warpBlocks, 256>>>(g1_as, g1_ad, N);
    gat_agg_kernel<<<N, 256>>>(g1_b, BUF_A, N);
    gnelu_kernel<<<warpBlocks, 256>>>(BUF_A, nullptr, n2_w, n2_b, BUF_A, N);

    // ---- GAT layer 2 : bufA -> (h=bufH) -> bufB ----
    mmagemm_kernel<false, false><<<dim3(HDIM / 64, mBlocks), 256>>>(
        BUF_A, nullptr, g2_w, nullptr, BUF_H, nullptr, N, HDIM);
    node_dots_kernel<<<warpBlocks, 256>>>(g2_as, g2_ad, N);
    gat_agg_kernel<<<N, 256>>>(g2_b, BUF_B, N);
    gnelu_kernel<<<warpBlocks, 256>>>(BUF_B, nullptr, n3_w, n3_b, BUF_B, N);

    // ---- lin2 accumulates into out (which already holds skip) ----
    mmagemm_kernel<true, true><<<dim3(COUT / 64, mBlocks), 256>>>(
        BUF_B, nullptr, lin2_w, lin2_b, BUF_EXT, out, N, COUT);
}

// round 12
// speedup vs baseline: 1.5565x; 1.4966x over previous
#include <cuda_runtime.h>
#include <cuda_bf16.h>
#include <math.h>
#include <stdint.h>

// ---------------- Problem-size constants (fixed by the dataset) -------------
#define NMAX   40000
#define EMAX   640000
#define ETMAX  (EMAX + NMAX)      // edges + self loops
#define CIN    256
#define HDIM   256
#define COUT   512
#define KDIM   256                // every GEMM in this model has K = 256

// ---------------- Static device scratch (no allocation allowed) -------------
__device__ float g_bufA[(size_t)NMAX * HDIM];
__device__ float g_bufB[(size_t)NMAX * HDIM];
__device__ float g_bufH[(size_t)NMAX * HDIM];
__device__ float g_asrc[NMAX];
__device__ float g_adst[NMAX];
__device__ int   g_deg[NMAX];
__device__ int   g_off[NMAX + 1];
__device__ int   g_cursor[NMAX];
__device__ int   g_srcs[ETMAX];
__device__ int   g_is64;          // 1 if edge_index is int64, 0 if int32
__device__ int   g_blksum[64];
__device__ int   g_blkoff[64];

// Buffer-id resolution (device side).
#define BUF_A 0
#define BUF_B 1
#define BUF_H 2
#define BUF_EXT (-1)

__device__ __forceinline__ float* resolve_buf(int id, float* ext)
{
    switch (id) {
        case BUF_A: return g_bufA;
        case BUF_B: return g_bufB;
        case BUF_H: return g_bufH;
        default:    return ext;
    }
}
__device__ __forceinline__ const float* resolve_cbuf(int id, const float* ext)
{
    switch (id) {
        case BUF_A: return g_bufA;
        case BUF_B: return g_bufB;
        case BUF_H: return g_bufH;
        default:    return ext;
    }
}

// ---------------- bf16 helpers ----------------------------------------------
// split a = hi + lo (both bf16); 3-pass MMA keeps hi*hi + hi*lo + lo*hi.
__device__ __forceinline__ void bf16_split(float a, __nv_bfloat16& hi, __nv_bfloat16& lo)
{
    hi = __float2bfloat16_rn(a);
    lo = __float2bfloat16_rn(a - __bfloat162float(hi));
}
__device__ __forceinline__ uint32_t pack_bf16(__nv_bfloat16 a, __nv_bfloat16 b)
{
    return (uint32_t)__bfloat16_as_ushort(a) | ((uint32_t)__bfloat16_as_ushort(b) << 16);
}

__device__ __forceinline__ void mma_bf16(float& c0, float& c1, float& c2, float& c3,
                                         uint32_t a0, uint32_t a1, uint32_t a2, uint32_t a3,
                                         uint32_t b0, uint32_t b1)
{
    asm volatile(
        "mma.sync.aligned.m16n8k16.row.col.f32.bf16.bf16.f32 "
        "{%0,%1,%2,%3}, {%4,%5,%6,%7}, {%8,%9}, {%0,%1,%2,%3};"
        : "+f"(c0), "+f"(c1), "+f"(c2), "+f"(c3)
        : "r"(a0), "r"(a1), "r"(a2), "r"(a3), "r"(b0), "r"(b1));
}

// =====================================================================
// 3-pass split-bf16 tensor-core GEMM:  C[m][j] = sum_k A[m][k]*W[j][k]
//   A: [Nrows, 256] row-major,  W: [J, 256] row-major.
// Tile BM=128, BN=64, BK=16; 256 threads = 8 warps in 4(M) x 2(N);
// each warp computes 32x32 via 2x4 m16n8k16 fragments.
// Register prefetch double-buffers the global loads.
// SMEM row stride: 24 bf16 = 48B -> (12r+q) mod 32 conflict-free.
// =====================================================================
#define SB   24    // row stride in bf16 elems
#define SB32 12    // row stride in u32

template <bool ACC, bool BIAS>
__global__ void __launch_bounds__(256)
bfgemm_kernel(int A_id, const float* __restrict__ A_ext,
              const float* __restrict__ W,
              const float* __restrict__ bias,
              int C_id, float* __restrict__ C_ext,
              int Nrows, int J)
{
    const float* A = resolve_cbuf(A_id, A_ext);
    float* C = resolve_buf(C_id, C_ext);

    __shared__ uint32_t As_hi[128 * SB32];
    __shared__ uint32_t As_lo[128 * SB32];
    __shared__ uint32_t Bs_hi[64 * SB32];
    __shared__ uint32_t Bs_lo[64 * SB32];

    int tid  = threadIdx.x;
    int wid  = tid >> 5;
    int lane = tid & 31;
    int grp  = lane >> 2;      // 0..7
    int qid  = lane & 3;       // 0..3

    int m0 = blockIdx.y * 128;
    int j0 = blockIdx.x * 64;

    int wm = (wid >> 1) * 32;  // warp M slab
    int wn = (wid & 1) * 32;   // warp N slab

    float acc[2][4][4];
#pragma unroll
    for (int i = 0; i < 2; i++)
#pragma unroll
        for (int j = 0; j < 4; j++)
#pragma unroll
            for (int q = 0; q < 4; q++) acc[i][j][q] = 0.f;

    // loader mapping
    int a_row  = tid >> 1;         // 0..127
    int a_half = tid & 1;          // k offset 0 / 8
    int b_row  = tid >> 2;         // 0..63
    int b_q    = tid & 3;          // k offset 0,4,8,12
    int a_grow = m0 + a_row;
    bool a_ok  = (a_grow < Nrows);
    const float* aptr = A + (size_t)a_grow * KDIM + a_half * 8;
    const float* bptr = W + (size_t)(j0 + b_row) * KDIM + b_q * 4;

    // store targets (u32 index), constant over loop
    uint32_t* a_sth = As_hi + a_row * SB32 + a_half * 4;
    uint32_t* a_stl = As_lo + a_row * SB32 + a_half * 4;
    uint32_t* b_sth = Bs_hi + b_row * SB32 + b_q * 2;
    uint32_t* b_stl = Bs_lo + b_row * SB32 + b_q * 2;

    // prefetch chunk 0
    float4 av0, av1, bv;
    av0 = a_ok ? *(const float4*)(aptr)     : make_float4(0.f, 0.f, 0.f, 0.f);
    av1 = a_ok ? *(const float4*)(aptr + 4) : make_float4(0.f, 0.f, 0.f, 0.f);
    bv  = *(const float4*)(bptr);

    for (int it = 0; it < 16; it++) {
        // ---- convert + store current chunk ----
        {
            float va[8] = {av0.x, av0.y, av0.z, av0.w, av1.x, av1.y, av1.z, av1.w};
            uint32_t wh[4], wl[4];
#pragma unroll
            for (int i = 0; i < 4; i++) {
                __nv_bfloat16 h0, l0, h1, l1;
                bf16_split(va[2 * i],     h0, l0);
                bf16_split(va[2 * i + 1], h1, l1);
                wh[i] = pack_bf16(h0, h1);
                wl[i] = pack_bf16(l0, l1);
            }
            *(uint4*)a_sth = make_uint4(wh[0], wh[1], wh[2], wh[3]);
            *(uint4*)a_stl = make_uint4(wl[0], wl[1], wl[2], wl[3]);

            float vb[4] = {bv.x, bv.y, bv.z, bv.w};
            __nv_bfloat16 h0, l0, h1, l1;
            bf16_split(vb[0], h0, l0); bf16_split(vb[1], h1, l1);
            uint32_t bh0 = pack_bf16(h0, h1), bl0 = pack_bf16(l0, l1);
            bf16_split(vb[2], h0, l0); bf16_split(vb[3], h1, l1);
            uint32_t bh1 = pack_bf16(h0, h1), bl1 = pack_bf16(l0, l1);
            *(uint2*)b_sth = make_uint2(bh0, bh1);
            *(uint2*)b_stl = make_uint2(bl0, bl1);
        }

        // ---- prefetch next chunk (LDGs in flight across the MMA phase) ----
        if (it < 15) {
            int k0 = (it + 1) * 16;
            av0 = a_ok ? *(const float4*)(aptr + k0)     : make_float4(0.f, 0.f, 0.f, 0.f);
            av1 = a_ok ? *(const float4*)(aptr + k0 + 4) : make_float4(0.f, 0.f, 0.f, 0.f);
            bv  = *(const float4*)(bptr + k0);
        }

        __syncthreads();

        // ---- fragment loads + MMA (one m16n8k16 covers the whole BK=16) ----
        uint32_t ah[2][4], al[2][4];
#pragma unroll
        for (int mt = 0; mt < 2; mt++) {
            int r0 = (wm + mt * 16 + grp) * SB32 + qid;
            int r1 = r0 + 8 * SB32;
            ah[mt][0] = As_hi[r0];     ah[mt][1] = As_hi[r1];
            ah[mt][2] = As_hi[r0 + 4]; ah[mt][3] = As_hi[r1 + 4];
            al[mt][0] = As_lo[r0];     al[mt][1] = As_lo[r1];
            al[mt][2] = As_lo[r0 + 4]; al[mt][3] = As_lo[r1 + 4];
        }
        uint32_t bh[4][2], bl[4][2];
#pragma unroll
        for (int nt = 0; nt < 4; nt++) {
            int rb = (wn + nt * 8 + grp) * SB32 + qid;
            bh[nt][0] = Bs_hi[rb]; bh[nt][1] = Bs_hi[rb + 4];
            bl[nt][0] = Bs_lo[rb]; bl[nt][1] = Bs_lo[rb + 4];
        }
#pragma unroll
        for (int mt = 0; mt < 2; mt++) {
#pragma unroll
            for (int nt = 0; nt < 4; nt++) {
                float* c = acc[mt][nt];
                mma_bf16(c[0], c[1], c[2], c[3],
                         ah[mt][0], ah[mt][1], ah[mt][2], ah[mt][3],
                         bh[nt][0], bh[nt][1]);
                mma_bf16(c[0], c[1], c[2], c[3],
                         ah[mt][0], ah[mt][1], ah[mt][2], ah[mt][3],
                         bl[nt][0], bl[nt][1]);
                mma_bf16(c[0], c[1], c[2], c[3],
                         al[mt][0], al[mt][1], al[mt][2], al[mt][3],
                         bh[nt][0], bh[nt][1]);
            }
        }
        __syncthreads();
    }

    // ---- epilogue ----
#pragma unroll
    for (int mt = 0; mt < 2; mt++) {
        int row0 = m0 + wm + mt * 16 + grp;
        int row1 = row0 + 8;
#pragma unroll
        for (int nt = 0; nt < 4; nt++) {
            int col = j0 + wn + nt * 8 + qid * 2;
            float b0 = 0.f, b1 = 0.f;
            if (BIAS) { b0 = bias[col]; b1 = bias[col + 1]; }
            if (row0 < Nrows) {
                float* p = C + (size_t)row0 * J + col;
                float v0 = acc[mt][nt][0] + b0;
                float v1 = acc[mt][nt][1] + b1;
                if (ACC) { v0 += p[0]; v1 += p[1]; }
                p[0] = v0; p[1] = v1;
            }
            if (row1 < Nrows) {
                float* p = C + (size_t)row1 * J + col;
                float v2 = acc[mt][nt][2] + b0;
                float v3 = acc[mt][nt][3] + b1;
                if (ACC) { v2 += p[0]; v3 += p[1]; }
                p[0] = v2; p[1] = v3;
            }
        }
    }
}

// Read edge endpoint idx (0..2E-1 flattened) honoring detected dtype.
__device__ __forceinline__ int edge_at(const void* ei, long long flat)
{
    if (g_is64) return (int)((const long long*)ei)[flat];
    return ((const int*)ei)[flat];
}

__global__ void detect_dtype_kernel(const void* ei, int n)
{
    if (threadIdx.x == 0 && blockIdx.x == 0) {
        const long long* p = (const long long*)ei;
        int ok = 1;
        for (int i = 0; i < 64; i++) {
            long long v = p[i];
            if (v < 0 || v >= n) { ok = 0; break; }
        }
        g_is64 = ok;
    }
}

// =====================================================================
// GroupNorm(groups = C/8) + ELU.  One warp per node; each lane owns one
// 8-channel group. C == 256.
// =====================================================================
__global__ void gnelu_kernel(int in_id, const float* __restrict__ in_ext,
                             const float* __restrict__ w,
                             const float* __restrict__ b,
                             int out_id, int n)
{
    const float* in = resolve_cbuf(in_id, in_ext);
    float* out = resolve_buf(out_id, nullptr);
    int warp = (blockIdx.x * blockDim.x + threadIdx.x) >> 5;
    int lane = threadIdx.x & 31;
    if (warp >= n) return;
    const float* row = in + (size_t)warp * 256;
    int c0 = lane * 8;
    float4 v0 = *(const float4*)(row + c0);
    float4 v1 = *(const float4*)(row + c0 + 4);
    float v[8] = {v0.x, v0.y, v0.z, v0.w, v1.x, v1.y, v1.z, v1.w};
    float mu = 0.f;
#pragma unroll
    for (int i = 0; i < 8; i++) mu += v[i];
    mu *= 0.125f;
    float var = 0.f;
#pragma unroll
    for (int i = 0; i < 8; i++) { float d = v[i] - mu; var += d * d; }
    var *= 0.125f;
    float inv = rsqrtf(var + 1e-5f);
    float* orow = out + (size_t)warp * 256;
#pragma unroll
    for (int i = 0; i < 8; i++) {
        float y = (v[i] - mu) * inv * w[c0 + i] + b[c0 + i];
        y = (y > 0.f) ? y : expm1f(y);
        v[i] = y;
    }
    *(float4*)(orow + c0)     = make_float4(v[0], v[1], v[2], v[3]);
    *(float4*)(orow + c0 + 4) = make_float4(v[4], v[5], v[6], v[7]);
}

// =====================================================================
// Per-node attention projections on h = g_bufH.  One warp per node.
// =====================================================================
__global__ void node_dots_kernel(const float* __restrict__ a_src,
                                 const float* __restrict__ a_dst, int n)
{
    int warp = (blockIdx.x * blockDim.x + threadIdx.x) >> 5;
    int lane = threadIdx.x & 31;
    if (warp >= n) return;
    const float* row = g_bufH + (size_t)warp * 256;
    float s1 = 0.f, s2 = 0.f;
#pragma unroll
    for (int i = 0; i < 8; i++) {
        int c = lane + i * 32;
        float v = row[c];
        s1 += v * a_src[c];
        s2 += v * a_dst[c];
    }
#pragma unroll
    for (int o = 16; o; o >>= 1) {
        s1 += __shfl_down_sync(0xffffffff, s1, o);
        s2 += __shfl_down_sync(0xffffffff, s2, o);
    }
    if (lane == 0) { g_asrc[warp] = s1; g_adst[warp] = s2; }
}

// ------------------------- CSR build kernels --------------------------------
__global__ void zero_deg_kernel(int n)
{
    int i = blockIdx.x * blockDim.x + threadIdx.x;
    if (i < n) g_deg[i] = 0;
}

__global__ void hist_kernel(const void* __restrict__ ei, int E, int n)
{
    int t = blockIdx.x * blockDim.x + threadIdx.x;
    if (t >= E + n) return;
    int d = (t < E) ? edge_at(ei, (long long)E + t) : (t - E);
    if ((unsigned)d >= (unsigned)n) return;
    atomicAdd(&g_deg[d], 1);
}

// ---- parallel 3-phase scan (coalesced) ----
// phase 1: per-block sums of 1024-element chunks
__global__ void scan1_kernel(int n)
{
    __shared__ int wsum[32];
    int tid = threadIdx.x;
    int i = blockIdx.x * 1024 + tid;
    int v = (i < n) ? g_deg[i] : 0;
    int s = v;
#pragma unroll
    for (int o = 16; o; o >>= 1) s += __shfl_down_sync(0xffffffff, s, o);
    if ((tid & 31) == 0) wsum[tid >> 5] = s;
    __syncthreads();
    if (tid < 32) {
        int t = wsum[tid];
#pragma unroll
        for (int o = 16; o; o >>= 1) t += __shfl_down_sync(0xffffffff, t, o);
        if (tid == 0) g_blksum[blockIdx.x] = t;
    }
}
// phase 2: exclusive scan of (<=64) block sums, single warp
__global__ void scan2_kernel(int nb)
{
    int tid = threadIdx.x;  // 64 threads
    int v = (tid < nb) ? g_blksum[tid] : 0;
    int x = v;
    // inclusive scan over 64 via two warps in smem
    __shared__ int sh[64];
    sh[tid] = v;
    __syncthreads();
    for (int o = 1; o < 64; o <<= 1) {
        int t = (tid >= o) ? sh[tid - o] : 0;
        __syncthreads();
        sh[tid] += t;
        __syncthreads();
    }
    if (tid < nb) g_blkoff[tid] = sh[tid] - x;  // exclusive
}
// phase 3: per-block exclusive scan + global offset; writes off & cursor
__global__ void scan3_kernel(int n)
{
    __shared__ int wsum[32];
    int tid = threadIdx.x;
    int lane = tid & 31, wid = tid >> 5;
    int i = blockIdx.x * 1024 + tid;
    int v = (i < n) ? g_deg[i] : 0;
    int x = v;
#pragma unroll
    for (int o = 1; o < 32; o <<= 1) {
        int t = __shfl_up_sync(0xffffffff, x, o);
        if (lane >= o) x += t;
    }
    if (lane == 31) wsum[wid] = x;
    __syncthreads();
    if (wid == 0) {
        int w = (lane < 32) ? wsum[lane] : 0;
#pragma unroll
        for (int o = 1; o < 32; o <<= 1) {
            int t = __shfl_up_sync(0xffffffff, w, o);
            if (lane >= o) w += t;
        }
        wsum[lane] = w;
    }
    __syncthreads();
    int excl = x - v + (wid ? wsum[wid - 1] : 0) + g_blkoff[blockIdx.x];
    if (i < n) {
        g_off[i] = excl;
        g_cursor[i] = excl;
        if (i == n - 1) g_off[n] = excl + v;
    }
}

__global__ void scatter_kernel(const void* __restrict__ ei, int E, int n)
{
    int t = blockIdx.x * blockDim.x + threadIdx.x;
    if (t >= E + n) return;
    int s, d;
    if (t < E) {
        s = edge_at(ei, t);
        d = edge_at(ei, (long long)E + t);
    } else {
        s = t - E; d = t - E;
    }
    if ((unsigned)d >= (unsigned)n || (unsigned)s >= (unsigned)n) return;
    int p = atomicAdd(&g_cursor[d], 1);
    g_srcs[p] = s;
}

// =====================================================================
// GAT aggregation: per destination node, segment softmax over incoming
// edges + weighted sum of source rows of h = g_bufH.  One block
// (256 thr) per node; thread t owns channel t.
// =====================================================================
__global__ void gat_agg_kernel(const float* __restrict__ bias, int out_id, int n)
{
    float* out = resolve_buf(out_id, nullptr);
    int node = blockIdx.x;
    int tid  = threadIdx.x;
    int s0 = g_off[node], s1 = g_off[node + 1];
    float ad = g_adst[node];

    __shared__ float red[256];

    float m = -1e30f;
    for (int j = s0 + tid; j < s1; j += 256) {
        float e = g_asrc[g_srcs[j]] + ad;
        e = (e > 0.f) ? e : 0.2f * e;
        m = fmaxf(m, e);
    }
    red[tid] = m;
    __syncthreads();
    for (int st = 128; st; st >>= 1) {
        if (tid < st) red[tid] = fmaxf(red[tid], red[tid + st]);
        __syncthreads();
    }
    m = red[0];
    __syncthreads();

    float s = 0.f;
    for (int j = s0 + tid; j < s1; j += 256) {
        float e = g_asrc[g_srcs[j]] + ad;
        e = (e > 0.f) ? e : 0.2f * e;
        s += expf(e - m);
    }
    red[tid] = s;
    __syncthreads();
    for (int st = 128; st; st >>= 1) {
        if (tid < st) red[tid] += red[tid + st];
        __syncthreads();
    }
    s = red[0];
    __syncthreads();
    float rinv = 1.0f / (s + 1e-16f);

    __shared__ float alpha_sh[128];
    __shared__ int   src_sh[128];
    float acc = 0.f;
    for (int base = s0; base < s1; base += 128) {
        int cnt = min(128, s1 - base);
        if (tid < cnt) {
            int sn = g_srcs[base + tid];
            src_sh[tid] = sn;
            float e = g_asrc[sn] + ad;
            e = (e > 0.f) ? e : 0.2f * e;
            alpha_sh[tid] = expf(e - m) * rinv;
        }
        __syncthreads();
        for (int j = 0; j < cnt; j++)
            acc += g_bufH[(size_t)src_sh[j] * 256 + tid] * alpha_sh[j];
        __syncthreads();
    }
    out[(size_t)node * 256 + tid] = acc + bias[tid];
}

// ============================== launcher =====================================
extern "C" void kernel_launch(void* const* d_in, const int* in_sizes, int n_in,
                              void* d_out, int out_size)
{
    const float* x      = (const float*)d_in[0];
    const void*  ei     = d_in[1];
    const float* pre_w  = (const float*)d_in[2];
    const float* pre_b  = (const float*)d_in[3];
    const float* lin1_w = (const float*)d_in[4];
    const float* lin1_b = (const float*)d_in[5];
    const float* n1_w   = (const float*)d_in[6];
    const float* n1_b   = (const float*)d_in[7];
    const float* g1_w   = (const float*)d_in[8];
    const float* g1_as  = (const float*)d_in[9];
    const float* g1_ad  = (const float*)d_in[10];
    const float* g1_b   = (const float*)d_in[11];
    const float* n2_w   = (const float*)d_in[12];
    const float* n2_b   = (const float*)d_in[13];
    const float* g2_w   = (const float*)d_in[14];
    const float* g2_as  = (const float*)d_in[15];
    const float* g2_ad  = (const float*)d_in[16];
    const float* g2_b   = (const float*)d_in[17];
    const float* n3_w   = (const float*)d_in[18];
    const float* n3_b   = (const float*)d_in[19];
    const float* lin2_w = (const float*)d_in[20];
    const float* lin2_b = (const float*)d_in[21];
    const float* skip_w = (const float*)d_in[22];
    const float* skip_b = (const float*)d_in[23];
    float* out = (float*)d_out;

    int N = in_sizes[0] / CIN;
    int E = in_sizes[1] / 2;
    int ET = E + N;

    int warpBlocks = (N * 32 + 255) / 256;
    int eBlocks    = (ET + 255) / 256;
    int nBlocks    = (N + 255) / 256;
    int mBlocks    = (N + 127) / 128;
    int sBlocks    = (N + 1023) / 1024;

    // ---- edge dtype detection + CSR build ----
    detect_dtype_kernel<<<1, 32>>>(ei, N);
    zero_deg_kernel<<<nBlocks, 256>>>(N);
    hist_kernel<<<eBlocks, 256>>>(ei, E, N);
    scan1_kernel<<<sBlocks, 1024>>>(N);
    scan2_kernel<<<1, 64>>>(sBlocks);

    // ---- skip GEMM (6th launch -> ncu profile target) ----
    bfgemm_kernel<false, true><<<dim3(COUT / 64, mBlocks), 256>>>(
        BUF_EXT, x, skip_w, skip_b, BUF_EXT, out, N, COUT);

    scan3_kernel<<<sBlocks, 1024>>>(N);
    scatter_kernel<<<eBlocks, 256>>>(ei, E, N);

    // ---- pre_norm + ELU : x -> bufA ----
    gnelu_kernel<<<warpBlocks, 256>>>(BUF_EXT, x, pre_w, pre_b, BUF_A, N);

    // ---- lin1 + GN + ELU : bufA -> bufB ----
    bfgemm_kernel<false, true><<<dim3(HDIM / 64, mBlocks), 256>>>(
        BUF_A, nullptr, lin1_w, lin1_b, BUF_B, nullptr, N, HDIM);
    gnelu_kernel<<<warpBlocks, 256>>>(BUF_B, nullptr, n1_w, n1_b, BUF_B, N);

    // ---- GAT layer 1 : bufB -> (h=bufH) -> bufA ----
    bfgemm_kernel<false, false><<<dim3(HDIM / 64, mBlocks), 256>>>(
        BUF_B, nullptr, g1_w, nullptr, BUF_H, nullptr, N, HDIM);
    node_dots_kernel<<<warpBlocks, 256>>>(g1_as, g1_ad, N);
    gat_agg_kernel<<<N, 256>>>(g1_b, BUF_A, N);
    gnelu_kernel<<<warpBlocks, 256>>>(BUF_A, nullptr, n2_w, n2_b, BUF_A, N);

    // ---- GAT layer 2 : bufA -> (h=bufH) -> bufB ----
    bfgemm_kernel<false, false><<<dim3(HDIM / 64, mBlocks), 256>>>(
        BUF_A, nullptr, g2_w, nullptr, BUF_H, nullptr, N, HDIM);
    node_dots_kernel<<<warpBlocks, 256>>>(g2_as, g2_ad, N);
    gat_agg_kernel<<<N, 256>>>(g2_b, BUF_B, N);
    gnelu_kernel<<<warpBlocks, 256>>>(BUF_B, nullptr, n3_w, n3_b, BUF_B, N);

    // ---- lin2 accumulates into out (which already holds skip) ----
    bfgemm_kernel<true, true><<<dim3(COUT / 64, mBlocks), 256>>>(
        BUF_B, nullptr, lin2_w, lin2_b, BUF_EXT, out, N, COUT);
}

// round 13
// speedup vs baseline: 1.6996x; 1.0919x over previous
#include <cuda_runtime.h>
#include <cuda_bf16.h>
#include <math.h>
#include <stdint.h>

// ---------------- Problem-size constants (fixed by the dataset) -------------
#define NMAX   40000
#define EMAX   640000
#define ETMAX  (EMAX + NMAX)      // edges + self loops
#define CIN    256
#define HDIM   256
#define COUT   512
#define KDIM   256                // every GEMM in this model has K = 256

// ---------------- Static device scratch (no allocation allowed) -------------
__device__ float g_bufA[(size_t)NMAX * HDIM];
__device__ float g_bufB[(size_t)NMAX * HDIM];
__device__ float g_bufH[(size_t)NMAX * HDIM];
__device__ float g_asrc[NMAX];
__device__ float g_adst[NMAX];
__device__ int   g_deg[NMAX];
__device__ int   g_off[NMAX + 1];
__device__ int   g_cursor[NMAX];
__device__ int   g_srcs[ETMAX];
__device__ int   g_is64;          // 1 if edge_index is int64, 0 if int32
__device__ int   g_blksum[64];
__device__ int   g_blkoff[64];

// Buffer-id resolution (device side).
#define BUF_A 0
#define BUF_B 1
#define BUF_H 2
#define BUF_EXT (-1)

__device__ __forceinline__ float* resolve_buf(int id, float* ext)
{
    switch (id) {
        case BUF_A: return g_bufA;
        case BUF_B: return g_bufB;
        case BUF_H: return g_bufH;
        default:    return ext;
    }
}
__device__ __forceinline__ const float* resolve_cbuf(int id, const float* ext)
{
    switch (id) {
        case BUF_A: return g_bufA;
        case BUF_B: return g_bufB;
        case BUF_H: return g_bufH;
        default:    return ext;
    }
}

// ---------------- bf16 helpers ----------------------------------------------
__device__ __forceinline__ void bf16_split(float a, __nv_bfloat16& hi, __nv_bfloat16& lo)
{
    hi = __float2bfloat16_rn(a);
    lo = __float2bfloat16_rn(a - __bfloat162float(hi));
}
__device__ __forceinline__ uint32_t pack_bf16(__nv_bfloat16 a, __nv_bfloat16 b)
{
    return (uint32_t)__bfloat16_as_ushort(a) | ((uint32_t)__bfloat16_as_ushort(b) << 16);
}

__device__ __forceinline__ void mma_bf16(float& c0, float& c1, float& c2, float& c3,
                                         uint32_t a0, uint32_t a1, uint32_t a2, uint32_t a3,
                                         uint32_t b0, uint32_t b1)
{
    asm volatile(
        "mma.sync.aligned.m16n8k16.row.col.f32.bf16.bf16.f32 "
        "{%0,%1,%2,%3}, {%4,%5,%6,%7}, {%8,%9}, {%0,%1,%2,%3};"
        : "+f"(c0), "+f"(c1), "+f"(c2), "+f"(c3)
        : "r"(a0), "r"(a1), "r"(a2), "r"(a3), "r"(b0), "r"(b1));
}

__device__ __forceinline__ float elu_f(float y)
{
    return (y > 0.f) ? y : expm1f(y);
}

// =====================================================================
// 3-pass split-bf16 tensor-core GEMM:  C[m][j] = sum_k A[m][k]*W[j][k]
// Tile BM=128, BN=64, BK=16; 256 threads = 8 warps in 4(M) x 2(N);
// each warp computes 32x32 via 2x4 m16n8k16 fragments.
// Register prefetch + smem ping-pong => one __syncthreads per K-iter.
// Optional fused GroupNorm(8)+ELU epilogue (groups of 8 channels live
// on one 4-lane quad => shfl_xor reductions, no smem).
// =====================================================================
#define SB32 12    // row stride in u32 (24 bf16 = 48B; (12r+q) mod 32 conflict-free)

template <bool ACC, bool BIAS, bool GNELU>
__global__ void __launch_bounds__(256)
bfgemm_kernel(int A_id, const float* __restrict__ A_ext,
              const float* __restrict__ W,
              const float* __restrict__ bias,
              const float* __restrict__ gn_w,
              const float* __restrict__ gn_b,
              int C_id, float* __restrict__ C_ext,
              int Nrows, int J)
{
    const float* A = resolve_cbuf(A_id, A_ext);
    float* C = resolve_buf(C_id, C_ext);

    __shared__ uint32_t As_hi[2][128 * SB32];
    __shared__ uint32_t As_lo[2][128 * SB32];
    __shared__ uint32_t Bs_hi[2][64 * SB32];
    __shared__ uint32_t Bs_lo[2][64 * SB32];

    int tid  = threadIdx.x;
    int wid  = tid >> 5;
    int lane = tid & 31;
    int grp  = lane >> 2;      // 0..7
    int qid  = lane & 3;       // 0..3

    int m0 = blockIdx.y * 128;
    int j0 = blockIdx.x * 64;

    int wm = (wid >> 1) * 32;  // warp M slab
    int wn = (wid & 1) * 32;   // warp N slab

    float acc[2][4][4];
#pragma unroll
    for (int i = 0; i < 2; i++)
#pragma unroll
        for (int j = 0; j < 4; j++)
#pragma unroll
            for (int q = 0; q < 4; q++) acc[i][j][q] = 0.f;

    // loader mapping
    int a_row  = tid >> 1;         // 0..127
    int a_half = tid & 1;          // k offset 0 / 8
    int b_row  = tid >> 2;         // 0..63
    int b_q    = tid & 3;          // k offset 0,4,8,12
    int a_grow = m0 + a_row;
    bool a_ok  = (a_grow < Nrows);
    const float* aptr = A + (size_t)a_grow * KDIM + a_half * 8;
    const float* bptr = W + (size_t)(j0 + b_row) * KDIM + b_q * 4;

    uint32_t a_st = a_row * SB32 + a_half * 4;
    uint32_t b_st = b_row * SB32 + b_q * 2;

    // prefetch chunk 0
    float4 av0, av1, bv;
    av0 = a_ok ? *(const float4*)(aptr)     : make_float4(0.f, 0.f, 0.f, 0.f);
    av1 = a_ok ? *(const float4*)(aptr + 4) : make_float4(0.f, 0.f, 0.f, 0.f);
    bv  = *(const float4*)(bptr);

    for (int it = 0; it < 16; it++) {
        int pp = it & 1;
        // ---- convert + store current chunk into ping-pong slot ----
        {
            float va[8] = {av0.x, av0.y, av0.z, av0.w, av1.x, av1.y, av1.z, av1.w};
            uint32_t wh[4], wl[4];
#pragma unroll
            for (int i = 0; i < 4; i++) {
                __nv_bfloat16 h0, l0, h1, l1;
                bf16_split(va[2 * i],     h0, l0);
                bf16_split(va[2 * i + 1], h1, l1);
                wh[i] = pack_bf16(h0, h1);
                wl[i] = pack_bf16(l0, l1);
            }
            *(uint4*)(As_hi[pp] + a_st) = make_uint4(wh[0], wh[1], wh[2], wh[3]);
            *(uint4*)(As_lo[pp] + a_st) = make_uint4(wl[0], wl[1], wl[2], wl[3]);

            float vb[4] = {bv.x, bv.y, bv.z, bv.w};
            __nv_bfloat16 h0, l0, h1, l1;
            bf16_split(vb[0], h0, l0); bf16_split(vb[1], h1, l1);
            uint32_t bh0 = pack_bf16(h0, h1), bl0 = pack_bf16(l0, l1);
            bf16_split(vb[2], h0, l0); bf16_split(vb[3], h1, l1);
            uint32_t bh1 = pack_bf16(h0, h1), bl1 = pack_bf16(l0, l1);
            *(uint2*)(Bs_hi[pp] + b_st) = make_uint2(bh0, bh1);
            *(uint2*)(Bs_lo[pp] + b_st) = make_uint2(bl0, bl1);
        }

        // ---- prefetch next chunk ----
        if (it < 15) {
            int k0 = (it + 1) * 16;
            av0 = a_ok ? *(const float4*)(aptr + k0)     : make_float4(0.f, 0.f, 0.f, 0.f);
            av1 = a_ok ? *(const float4*)(aptr + k0 + 4) : make_float4(0.f, 0.f, 0.f, 0.f);
            bv  = *(const float4*)(bptr + k0);
        }

        __syncthreads();   // single barrier per iter (ping-pong protects reuse)

        // ---- fragment loads + MMA ----
        uint32_t ah[2][4], al[2][4];
#pragma unroll
        for (int mt = 0; mt < 2; mt++) {
            int r0 = (wm + mt * 16 + grp) * SB32 + qid;
            int r1 = r0 + 8 * SB32;
            ah[mt][0] = As_hi[pp][r0];     ah[mt][1] = As_hi[pp][r1];
            ah[mt][2] = As_hi[pp][r0 + 4]; ah[mt][3] = As_hi[pp][r1 + 4];
            al[mt][0] = As_lo[pp][r0];     al[mt][1] = As_lo[pp][r1];
            al[mt][2] = As_lo[pp][r0 + 4]; al[mt][3] = As_lo[pp][r1 + 4];
        }
        uint32_t bh[4][2], bl[4][2];
#pragma unroll
        for (int nt = 0; nt < 4; nt++) {
            int rb = (wn + nt * 8 + grp) * SB32 + qid;
            bh[nt][0] = Bs_hi[pp][rb]; bh[nt][1] = Bs_hi[pp][rb + 4];
            bl[nt][0] = Bs_lo[pp][rb]; bl[nt][1] = Bs_lo[pp][rb + 4];
        }
#pragma unroll
        for (int mt = 0; mt < 2; mt++) {
#pragma unroll
            for (int nt = 0; nt < 4; nt++) {
                float* c = acc[mt][nt];
                mma_bf16(c[0], c[1], c[2], c[3],
                         ah[mt][0], ah[mt][1], ah[mt][2], ah[mt][3],
                         bh[nt][0], bh[nt][1]);
                mma_bf16(c[0], c[1], c[2], c[3],
                         ah[mt][0], ah[mt][1], ah[mt][2], ah[mt][3],
                         bl[nt][0], bl[nt][1]);
                mma_bf16(c[0], c[1], c[2], c[3],
                         al[mt][0], al[mt][1], al[mt][2], al[mt][3],
                         bh[nt][0], bh[nt][1]);
            }
        }
    }

    // ---- epilogue (optionally fused GroupNorm(8)+ELU) ----
#pragma unroll
    for (int mt = 0; mt < 2; mt++) {
        int row0 = m0 + wm + mt * 16 + grp;
        int row1 = row0 + 8;
#pragma unroll
        for (int nt = 0; nt < 4; nt++) {
            int col = j0 + wn + nt * 8 + qid * 2;
            float b0 = 0.f, b1 = 0.f;
            if (BIAS) { b0 = bias[col]; b1 = bias[col + 1]; }
            float v0 = acc[mt][nt][0] + b0;
            float v1 = acc[mt][nt][1] + b1;
            float v2 = acc[mt][nt][2] + b0;
            float v3 = acc[mt][nt][3] + b1;
            if (GNELU) {
                // row0 group (8 channels across the 4-lane quad)
                float s01 = v0 + v1, q01 = v0 * v0 + v1 * v1;
                float s23 = v2 + v3, q23 = v2 * v2 + v3 * v3;
                s01 += __shfl_xor_sync(0xffffffffu, s01, 1);
                q01 += __shfl_xor_sync(0xffffffffu, q01, 1);
                s23 += __shfl_xor_sync(0xffffffffu, s23, 1);
                q23 += __shfl_xor_sync(0xffffffffu, q23, 1);
                s01 += __shfl_xor_sync(0xffffffffu, s01, 2);
                q01 += __shfl_xor_sync(0xffffffffu, q01, 2);
                s23 += __shfl_xor_sync(0xffffffffu, s23, 2);
                q23 += __shfl_xor_sync(0xffffffffu, q23, 2);
                float mu0 = s01 * 0.125f;
                float iv0 = rsqrtf(q01 * 0.125f - mu0 * mu0 + 1e-5f);
                float mu1 = s23 * 0.125f;
                float iv1 = rsqrtf(q23 * 0.125f - mu1 * mu1 + 1e-5f);
                float w0 = gn_w[col], w1 = gn_w[col + 1];
                float gb0 = gn_b[col], gb1 = gn_b[col + 1];
                v0 = elu_f((v0 - mu0) * iv0 * w0 + gb0);
                v1 = elu_f((v1 - mu0) * iv0 * w1 + gb1);
                v2 = elu_f((v2 - mu1) * iv1 * w0 + gb0);
                v3 = elu_f((v3 - mu1) * iv1 * w1 + gb1);
            }
            if (row0 < Nrows) {
                float* p = C + (size_t)row0 * J + col;
                if (ACC) { v0 += p[0]; v1 += p[1]; }
                p[0] = v0; p[1] = v1;
            }
            if (row1 < Nrows) {
                float* p = C + (size_t)row1 * J + col;
                if (ACC) { v2 += p[0]; v3 += p[1]; }
                p[0] = v2; p[1] = v3;
            }
        }
    }
}

// Read edge endpoint idx (0..2E-1 flattened) honoring detected dtype.
__device__ __forceinline__ int edge_at(const void* ei, long long flat)
{
    if (g_is64) return (int)((const long long*)ei)[flat];
    return ((const int*)ei)[flat];
}

__global__ void detect_dtype_kernel(const void* ei, int n)
{
    if (threadIdx.x == 0 && blockIdx.x == 0) {
        const long long* p = (const long long*)ei;
        int ok = 1;
        for (int i = 0; i < 64; i++) {
            long long v = p[i];
            if (v < 0 || v >= n) { ok = 0; break; }
        }
        g_is64 = ok;
    }
}

// =====================================================================
// GroupNorm(groups = C/8) + ELU (standalone; used only for pre_norm).
// =====================================================================
__global__ void gnelu_kernel(int in_id, const float* __restrict__ in_ext,
                             const float* __restrict__ w,
                             const float* __restrict__ b,
                             int out_id, int n)
{
    const float* in = resolve_cbuf(in_id, in_ext);
    float* out = resolve_buf(out_id, nullptr);
    int warp = (blockIdx.x * blockDim.x + threadIdx.x) >> 5;
    int lane = threadIdx.x & 31;
    if (warp >= n) return;
    const float* row = in + (size_t)warp * 256;
    int c0 = lane * 8;
    float4 v0 = *(const float4*)(row + c0);
    float4 v1 = *(const float4*)(row + c0 + 4);
    float v[8] = {v0.x, v0.y, v0.z, v0.w, v1.x, v1.y, v1.z, v1.w};
    float mu = 0.f;
#pragma unroll
    for (int i = 0; i < 8; i++) mu += v[i];
    mu *= 0.125f;
    float var = 0.f;
#pragma unroll
    for (int i = 0; i < 8; i++) { float d = v[i] - mu; var += d * d; }
    var *= 0.125f;
    float inv = rsqrtf(var + 1e-5f);
    float* orow = out + (size_t)warp * 256;
#pragma unroll
    for (int i = 0; i < 8; i++)
        v[i] = elu_f((v[i] - mu) * inv * w[c0 + i] + b[c0 + i]);
    *(float4*)(orow + c0)     = make_float4(v[0], v[1], v[2], v[3]);
    *(float4*)(orow + c0 + 4) = make_float4(v[4], v[5], v[6], v[7]);
}

// =====================================================================
// Per-node attention projections on h = g_bufH.  One warp per node.
// =====================================================================
__global__ void node_dots_kernel(const float* __restrict__ a_src,
                                 const float* __restrict__ a_dst, int n)
{
    int warp = (blockIdx.x * blockDim.x + threadIdx.x) >> 5;
    int lane = threadIdx.x & 31;
    if (warp >= n) return;
    const float* row = g_bufH + (size_t)warp * 256;
    float s1 = 0.f, s2 = 0.f;
#pragma unroll
    for (int i = 0; i < 8; i++) {
        int c = lane + i * 32;
        float v = row[c];
        s1 += v * a_src[c];
        s2 += v * a_dst[c];
    }
#pragma unroll
    for (int o = 16; o; o >>= 1) {
        s1 += __shfl_down_sync(0xffffffff, s1, o);
        s2 += __shfl_down_sync(0xffffffff, s2, o);
    }
    if (lane == 0) { g_asrc[warp] = s1; g_adst[warp] = s2; }
}

// ------------------------- CSR build kernels --------------------------------
__global__ void zero_deg_kernel(int n)
{
    int i = blockIdx.x * blockDim.x + threadIdx.x;
    if (i < n) g_deg[i] = 0;
}

__global__ void hist_kernel(const void* __restrict__ ei, int E, int n)
{
    int t = blockIdx.x * blockDim.x + threadIdx.x;
    if (t >= E + n) return;
    int d = (t < E) ? edge_at(ei, (long long)E + t) : (t - E);
    if ((unsigned)d >= (unsigned)n) return;
    atomicAdd(&g_deg[d], 1);
}

// ---- parallel 3-phase scan ----
__global__ void scan1_kernel(int n)
{
    __shared__ int wsum[32];
    int tid = threadIdx.x;
    int i = blockIdx.x * 1024 + tid;
    int v = (i < n) ? g_deg[i] : 0;
    int s = v;
#pragma unroll
    for (int o = 16; o; o >>= 1) s += __shfl_down_sync(0xffffffff, s, o);
    if ((tid & 31) == 0) wsum[tid >> 5] = s;
    __syncthreads();
    if (tid < 32) {
        int t = wsum[tid];
#pragma unroll
        for (int o = 16; o; o >>= 1) t += __shfl_down_sync(0xffffffff, t, o);
        if (tid == 0) g_blksum[blockIdx.x] = t;
    }
}
__global__ void scan2_kernel(int nb)
{
    int tid = threadIdx.x;  // 64 threads
    int v = (tid < nb) ? g_blksum[tid] : 0;
    int x = v;
    __shared__ int sh[64];
    sh[tid] = v;
    __syncthreads();
    for (int o = 1; o < 64; o <<= 1) {
        int t = (tid >= o) ? sh[tid - o] : 0;
        __syncthreads();
        sh[tid] += t;
        __syncthreads();
    }
    if (tid < nb) g_blkoff[tid] = sh[tid] - x;  // exclusive
}
__global__ void scan3_kernel(int n)
{
    __shared__ int wsum[32];
    int tid = threadIdx.x;
    int lane = tid & 31, wid = tid >> 5;
    int i = blockIdx.x * 1024 + tid;
    int v = (i < n) ? g_deg[i] : 0;
    int x = v;
#pragma unroll
    for (int o = 1; o < 32; o <<= 1) {
        int t = __shfl_up_sync(0xffffffff, x, o);
        if (lane >= o) x += t;
    }
    if (lane == 31) wsum[wid] = x;
    __syncthreads();
    if (wid == 0) {
        int w = wsum[lane];
#pragma unroll
        for (int o = 1; o < 32; o <<= 1) {
            int t = __shfl_up_sync(0xffffffff, w, o);
            if (lane >= o) w += t;
        }
        wsum[lane] = w;
    }
    __syncthreads();
    int excl = x - v + (wid ? wsum[wid - 1] : 0) + g_blkoff[blockIdx.x];
    if (i < n) {
        g_off[i] = excl;
        g_cursor[i] = excl;
        if (i == n - 1) g_off[n] = excl + v;
    }
}

__global__ void scatter_kernel(const void* __restrict__ ei, int E, int n)
{
    int t = blockIdx.x * blockDim.x + threadIdx.x;
    if (t >= E + n) return;
    int s, d;
    if (t < E) {
        s = edge_at(ei, t);
        d = edge_at(ei, (long long)E + t);
    } else {
        s = t - E; d = t - E;
    }
    if ((unsigned)d >= (unsigned)n || (unsigned)s >= (unsigned)n) return;
    int p = atomicAdd(&g_cursor[d], 1);
    g_srcs[p] = s;
}

// =====================================================================
// GAT aggregation + fused GroupNorm(8)+ELU.  One block (256 thr) per
// node; thread t owns channel t; GN group = 8 consecutive lanes.
// =====================================================================
__global__ void gat_agg_kernel(const float* __restrict__ bias,
                               const float* __restrict__ gn_w,
                               const float* __restrict__ gn_b,
                               int out_id, int n)
{
    float* out = resolve_buf(out_id, nullptr);
    int node = blockIdx.x;
    int tid  = threadIdx.x;
    int s0 = g_off[node], s1 = g_off[node + 1];
    float ad = g_adst[node];

    __shared__ float red[256];

    float m = -1e30f;
    for (int j = s0 + tid; j < s1; j += 256) {
        float e = g_asrc[g_srcs[j]] + ad;
        e = (e > 0.f) ? e : 0.2f * e;
        m = fmaxf(m, e);
    }
    red[tid] = m;
    __syncthreads();
    for (int st = 128; st; st >>= 1) {
        if (tid < st) red[tid] = fmaxf(red[tid], red[tid + st]);
        __syncthreads();
    }
    m = red[0];
    __syncthreads();

    float s = 0.f;
    for (int j = s0 + tid; j < s1; j += 256) {
        float e = g_asrc[g_srcs[j]] + ad;
        e = (e > 0.f) ? e : 0.2f * e;
        s += expf(e - m);
    }
    red[tid] = s;
    __syncthreads();
    for (int st = 128; st; st >>= 1) {
        if (tid < st) red[tid] += red[tid + st];
        __syncthreads();
    }
    s = red[0];
    __syncthreads();
    float rinv = 1.0f / (s + 1e-16f);

    __shared__ float alpha_sh[128];
    __shared__ int   src_sh[128];
    float acc = 0.f;
    for (int base = s0; base < s1; base += 128) {
        int cnt = min(128, s1 - base);
        if (tid < cnt) {
            int sn = g_srcs[base + tid];
            src_sh[tid] = sn;
            float e = g_asrc[sn] + ad;
            e = (e > 0.f) ? e : 0.2f * e;
            alpha_sh[tid] = expf(e - m) * rinv;
        }
        __syncthreads();
        for (int j = 0; j < cnt; j++)
            acc += g_bufH[(size_t)src_sh[j] * 256 + tid] * alpha_sh[j];
        __syncthreads();
    }

    // fused GroupNorm(8)+ELU on (acc + bias)
    float o = acc + bias[tid];
    float su = o, sq = o * o;
    su += __shfl_xor_sync(0xffffffffu, su, 1);
    sq += __shfl_xor_sync(0xffffffffu, sq, 1);
    su += __shfl_xor_sync(0xffffffffu, su, 2);
    sq += __shfl_xor_sync(0xffffffffu, sq, 2);
    su += __shfl_xor_sync(0xffffffffu, su, 4);
    sq += __shfl_xor_sync(0xffffffffu, sq, 4);
    float mu = su * 0.125f;
    float iv = rsqrtf(sq * 0.125f - mu * mu + 1e-5f);
    float y = elu_f((o - mu) * iv * gn_w[tid] + gn_b[tid]);
    out[(size_t)node * 256 + tid] = y;
}

// ============================== launcher =====================================
extern "C" void kernel_launch(void* const* d_in, const int* in_sizes, int n_in,
                              void* d_out, int out_size)
{
    const float* x      = (const float*)d_in[0];
    const void*  ei     = d_in[1];
    const float* pre_w  = (const float*)d_in[2];
    const float* pre_b  = (const float*)d_in[3];
    const float* lin1_w = (const float*)d_in[4];
    const float* lin1_b = (const float*)d_in[5];
    const float* n1_w   = (const float*)d_in[6];
    const float* n1_b   = (const float*)d_in[7];
    const float* g1_w   = (const float*)d_in[8];
    const float* g1_as  = (const float*)d_in[9];
    const float* g1_ad  = (const float*)d_in[10];
    const float* g1_b   = (const float*)d_in[11];
    const float* n2_w   = (const float*)d_in[12];
    const float* n2_b   = (const float*)d_in[13];
    const float* g2_w   = (const float*)d_in[14];
    const float* g2_as  = (const float*)d_in[15];
    const float* g2_ad  = (const float*)d_in[16];
    const float* g2_b   = (const float*)d_in[17];
    const float* n3_w   = (const float*)d_in[18];
    const float* n3_b   = (const float*)d_in[19];
    const float* lin2_w = (const float*)d_in[20];
    const float* lin2_b = (const float*)d_in[21];
    const float* skip_w = (const float*)d_in[22];
    const float* skip_b = (const float*)d_in[23];
    float* out = (float*)d_out;

    int N = in_sizes[0] / CIN;
    int E = in_sizes[1] / 2;
    int ET = E + N;

    int warpBlocks = (N * 32 + 255) / 256;
    int eBlocks    = (ET + 255) / 256;
    int nBlocks    = (N + 255) / 256;
    int mBlocks    = (N + 127) / 128;
    int sBlocks    = (N + 1023) / 1024;

    // ---- edge dtype detection + CSR build; skip GEMM at slot 4 for ncu ----
    detect_dtype_kernel<<<1, 32>>>(ei, N);
    zero_deg_kernel<<<nBlocks, 256>>>(N);
    hist_kernel<<<eBlocks, 256>>>(ei, E, N);

    bfgemm_kernel<false, true, false><<<dim3(COUT / 64, mBlocks), 256>>>(
        BUF_EXT, x, skip_w, skip_b, nullptr, nullptr, BUF_EXT, out, N, COUT);

    scan1_kernel<<<sBlocks, 1024>>>(N);
    scan2_kernel<<<1, 64>>>(sBlocks);
    scan3_kernel<<<sBlocks, 1024>>>(N);
    scatter_kernel<<<eBlocks, 256>>>(ei, E, N);

    // ---- pre_norm + ELU : x -> bufA ----
    gnelu_kernel<<<warpBlocks, 256>>>(BUF_EXT, x, pre_w, pre_b, BUF_A, N);

    // ---- lin1 (+ fused GN1+ELU) : bufA -> bufB ----
    bfgemm_kernel<false, true, true><<<dim3(HDIM / 64, mBlocks), 256>>>(
        BUF_A, nullptr, lin1_w, lin1_b, n1_w, n1_b, BUF_B, nullptr, N, HDIM);

    // ---- GAT layer 1 : bufB -> (h=bufH) -> bufA (agg + fused GN2+ELU) ----
    bfgemm_kernel<false, false, false><<<dim3(HDIM / 64, mBlocks), 256>>>(
        BUF_B, nullptr, g1_w, nullptr, nullptr, nullptr, BUF_H, nullptr, N, HDIM);
    node_dots_kernel<<<warpBlocks, 256>>>(g1_as, g1_ad, N);
    gat_agg_kernel<<<N, 256>>>(g1_b, n2_w, n2_b, BUF_A, N);

    // ---- GAT layer 2 : bufA -> (h=bufH) -> bufB (agg + fused GN3+ELU) ----
    bfgemm_kernel<false, false, false><<<dim3(HDIM / 64, mBlocks), 256>>>(
        BUF_A, nullptr, g2_w, nullptr, nullptr, nullptr, BUF_H, nullptr, N, HDIM);
    node_dots_kernel<<<warpBlocks, 256>>>(g2_as, g2_ad, N);
    gat_agg_kernel<<<N, 256>>>(g2_b, n3_w, n3_b, BUF_B, N);

    // ---- lin2 accumulates into out (which already holds skip) ----
    bfgemm_kernel<true, true, false><<<dim3(COUT / 64, mBlocks), 256>>>(
        BUF_B, nullptr, lin2_w, lin2_b, nullptr, nullptr, BUF_EXT, out, N, COUT);
}